// round 1
// baseline (speedup 1.0000x reference)
#include <cuda_runtime.h>

#define NW 10
#define DIM 1024
#define WARPS_PER_BLK 4

// XOR swizzle for conflict-free 32x32 float2 transpose through shared memory:
// column (low 5 bits) ^= row (high 5 bits).
__device__ __forceinline__ int swz(int idx) {
    return (idx & 0x3E0) | (((idx >> 5) ^ idx) & 31);
}

// CNOT-ring gather: psi_after[i] = psi_before[g(i)]
// Derived from sequential ring CNOT(j -> j+1 mod 10), qubit k bit at position 9-k:
//   g bit p (p=0..7) = b_p ^ b_{p+1};  g bit8 = b8^b9^b0;  g bit9 = b9^b0.
__device__ __forceinline__ int cnot_gather(int i) {
    return i ^ (i >> 1) ^ ((i & 1) << 8) ^ ((i & 1) << 9);
}

// Fused layer-1 gate M = RY(ry0)*RX(rx0) = [[a, b], [-conj(b), conj(a)]]
// applied on register bit K of the 32-amplitude per-thread slice.
template<int K>
__device__ __forceinline__ void apply_l1(float2* a, float ar, float ai, float br, float bi) {
#pragma unroll
    for (int p = 0; p < 16; ++p) {
        const int m0 = ((p >> K) << (K + 1)) | (p & ((1 << K) - 1));
        const int m1 = m0 | (1 << K);
        float2 a0 = a[m0], a1 = a[m1];
        float n0r =  ar * a0.x - ai * a0.y + br * a1.x - bi * a1.y;
        float n0i =  ar * a0.y + ai * a0.x + br * a1.y + bi * a1.x;
        float n1r = -br * a0.x - bi * a0.y + ar * a1.x + ai * a1.y;
        float n1i = -br * a0.y + bi * a0.x + ar * a1.y - ai * a1.x;
        a[m0] = make_float2(n0r, n0i);
        a[m1] = make_float2(n1r, n1i);
    }
}

// RY gate (real rotation) on register bit K.
template<int K>
__device__ __forceinline__ void apply_ry(float2* a, float c, float s) {
#pragma unroll
    for (int p = 0; p < 16; ++p) {
        const int m0 = ((p >> K) << (K + 1)) | (p & ((1 << K) - 1));
        const int m1 = m0 | (1 << K);
        float2 a0 = a[m0], a1 = a[m1];
        a[m0] = make_float2(c * a0.x - s * a1.x, c * a0.y - s * a1.y);
        a[m1] = make_float2(s * a0.x + c * a1.x, s * a0.y + c * a1.y);
    }
}

__global__ __launch_bounds__(128, 4)
void qsa_kernel(const float* __restrict__ x,
                const float* __restrict__ rx0,
                const float* __restrict__ ry0,
                const float* __restrict__ ry1,
                float* __restrict__ out)
{
    __shared__ float2 buf[WARPS_PER_BLK][DIM];   // per-warp transpose buffer
    __shared__ float coef[NW][6];                // ar, ai, br, bi, c1, s1 per wire

    const int tid = threadIdx.x;

    // Per-block gate coefficient computation (cheap, avoids a prep kernel).
    if (tid < NW) {
        float s, c, s0, c0, s1, c1;
        sincosf(0.5f * rx0[tid], &s,  &c);
        sincosf(0.5f * ry0[tid], &s0, &c0);
        sincosf(0.5f * ry1[tid], &s1, &c1);
        coef[tid][0] =  c0 * c;   // alpha.re
        coef[tid][1] =  s0 * s;   // alpha.im
        coef[tid][2] = -s0 * c;   // beta.re
        coef[tid][3] = -c0 * s;   // beta.im
        coef[tid][4] =  c1;
        coef[tid][5] =  s1;
    }
    __syncthreads();

    const int w = tid >> 5;
    const int t = tid & 31;
    const int n = blockIdx.x * WARPS_PER_BLK + w;   // state index 0..4095
    float2* sb = buf[w];

    // ---- Load + L2-normalize. Layout LA: index i = (r<<5) | t  (coalesced). ----
    float2 a[32];
    const float* xr = x + n * DIM;
    float sumsq = 0.f;
#pragma unroll
    for (int r = 0; r < 32; ++r) {
        float v = xr[(r << 5) + t];
        a[r] = make_float2(v, 0.f);
        sumsq += v * v;
    }
#pragma unroll
    for (int off = 16; off; off >>= 1)
        sumsq += __shfl_xor_sync(0xffffffffu, sumsq, off);
    const float inv = 1.f / fmaxf(sqrtf(sumsq), 1e-12f);
#pragma unroll
    for (int r = 0; r < 32; ++r) a[r].x *= inv;

    // ---- Phase A: fused layer-1 on wires 0..4 (LA register bits p5..p9; wire q -> K=4-q) ----
    apply_l1<4>(a, coef[0][0], coef[0][1], coef[0][2], coef[0][3]);
    apply_l1<3>(a, coef[1][0], coef[1][1], coef[1][2], coef[1][3]);
    apply_l1<2>(a, coef[2][0], coef[2][1], coef[2][2], coef[2][3]);
    apply_l1<1>(a, coef[3][0], coef[3][1], coef[3][2], coef[3][3]);
    apply_l1<0>(a, coef[4][0], coef[4][1], coef[4][2], coef[4][3]);

    // ---- Remap LA -> LB (transpose) ----
    __syncwarp();
#pragma unroll
    for (int r = 0; r < 32; ++r) sb[swz((r << 5) | t)] = a[r];
    __syncwarp();
#pragma unroll
    for (int r = 0; r < 32; ++r) a[r] = sb[swz((t << 5) | r)];

    // ---- Phase B: fused layer-1 on wires 5..9 (LB register bits p0..p4; wire q -> K=9-q) ----
    apply_l1<4>(a, coef[5][0], coef[5][1], coef[5][2], coef[5][3]);
    apply_l1<3>(a, coef[6][0], coef[6][1], coef[6][2], coef[6][3]);
    apply_l1<2>(a, coef[7][0], coef[7][1], coef[7][2], coef[7][3]);
    apply_l1<1>(a, coef[8][0], coef[8][1], coef[8][2], coef[8][3]);
    apply_l1<0>(a, coef[9][0], coef[9][1], coef[9][2], coef[9][3]);

    // ---- Remap LB -> LA with the CNOT-ring permutation folded into the gather ----
    __syncwarp();
#pragma unroll
    for (int r = 0; r < 32; ++r) sb[swz((t << 5) | r)] = a[r];
    __syncwarp();
#pragma unroll
    for (int r = 0; r < 32; ++r) {
        const int i2 = (r << 5) | t;
        a[r] = sb[swz(cnot_gather(i2))];
    }

    // ---- Phase C: layer-2 RY on wires 0..4 ----
    apply_ry<4>(a, coef[0][4], coef[0][5]);
    apply_ry<3>(a, coef[1][4], coef[1][5]);
    apply_ry<2>(a, coef[2][4], coef[2][5]);
    apply_ry<1>(a, coef[3][4], coef[3][5]);
    apply_ry<0>(a, coef[4][4], coef[4][5]);

    // ---- Remap LA -> LB (transpose) ----
    __syncwarp();
#pragma unroll
    for (int r = 0; r < 32; ++r) sb[swz((r << 5) | t)] = a[r];
    __syncwarp();
#pragma unroll
    for (int r = 0; r < 32; ++r) a[r] = sb[swz((t << 5) | r)];

    // ---- Phase D: layer-2 RY on wires 5..9 ----
    apply_ry<4>(a, coef[5][4], coef[5][5]);
    apply_ry<3>(a, coef[6][4], coef[6][5]);
    apply_ry<2>(a, coef[7][4], coef[7][5]);
    apply_ry<1>(a, coef[8][4], coef[8][5]);
    apply_ry<0>(a, coef[9][4], coef[9][5]);

    // ---- Z expectations. Layout LB: i = (t<<5) | r.
    // Wires 5..9 depend on r bits (per-thread signed sums), wires 0..4 on t bits.
    float tot = 0.f, S0 = 0.f, S1 = 0.f, S2 = 0.f, S3 = 0.f, S4 = 0.f;
#pragma unroll
    for (int r = 0; r < 32; ++r) {
        float p = a[r].x * a[r].x + a[r].y * a[r].y;
        tot += p;
        S0 += (r & 1)  ? -p : p;
        S1 += (r & 2)  ? -p : p;
        S2 += (r & 4)  ? -p : p;
        S3 += (r & 8)  ? -p : p;
        S4 += (r & 16) ? -p : p;
    }
    float vals[10];
    vals[0] = (t & 16) ? -tot : tot;   // wire 0: t bit 4
    vals[1] = (t & 8)  ? -tot : tot;
    vals[2] = (t & 4)  ? -tot : tot;
    vals[3] = (t & 2)  ? -tot : tot;
    vals[4] = (t & 1)  ? -tot : tot;
    vals[5] = S4;                      // wire 5: r bit 4
    vals[6] = S3;
    vals[7] = S2;
    vals[8] = S1;
    vals[9] = S0;
#pragma unroll
    for (int off = 16; off; off >>= 1) {
#pragma unroll
        for (int j = 0; j < 10; ++j)
            vals[j] += __shfl_xor_sync(0xffffffffu, vals[j], off);
    }
    if (t == 0) {
#pragma unroll
        for (int j = 0; j < 10; ++j) out[n * NW + j] = vals[j];
    }
}

extern "C" void kernel_launch(void* const* d_in, const int* in_sizes, int n_in,
                              void* d_out, int out_size) {
    const float* x   = (const float*)d_in[0];
    const float* rx0 = (const float*)d_in[1];
    const float* ry0 = (const float*)d_in[2];
    const float* ry1 = (const float*)d_in[3];
    float* out = (float*)d_out;
    const int n_states = in_sizes[0] / DIM;          // 4096
    qsa_kernel<<<n_states / WARPS_PER_BLK, 32 * WARPS_PER_BLK>>>(x, rx0, ry0, ry1, out);
}

// round 2
// speedup vs baseline: 1.0114x; 1.0114x over previous
#include <cuda_runtime.h>

#define NW 10
#define DIM 1024
#define WARPS_PER_BLK 4

typedef unsigned long long u64;

// ---- packed f32x2 primitives (sm_100+; ptxas never auto-fuses these) ----
__device__ __forceinline__ u64 pk(float x, float y) {
    u64 r; asm("mov.b64 %0,{%1,%2};" : "=l"(r) : "f"(x), "f"(y)); return r;
}
__device__ __forceinline__ u64 pkb(float x) { return pk(x, x); }   // broadcast
__device__ __forceinline__ void upk(u64 a, float& x, float& y) {
    asm("mov.b64 {%0,%1},%2;" : "=f"(x), "=f"(y) : "l"(a));
}
__device__ __forceinline__ u64 f2fma(u64 a, u64 b, u64 c) {
    u64 d; asm("fma.rn.f32x2 %0,%1,%2,%3;" : "=l"(d) : "l"(a), "l"(b), "l"(c)); return d;
}
__device__ __forceinline__ u64 f2mul(u64 a, u64 b) {
    u64 d; asm("mul.rn.f32x2 %0,%1,%2;" : "=l"(d) : "l"(a), "l"(b)); return d;
}
__device__ __forceinline__ u64 f2add(u64 a, u64 b) {
    u64 d; asm("add.rn.f32x2 %0,%1,%2;" : "=l"(d) : "l"(a), "l"(b)); return d;
}

// XOR swizzle for conflict-free 32x32 8-byte transpose through shared memory.
__device__ __forceinline__ int swz(int idx) {
    return (idx & 0x3E0) | (((idx >> 5) ^ idx) & 31);
}

// CNOT-ring gather: psi_after[i] = psi_before[g(i)]
__device__ __forceinline__ int cnot_gather(int i) {
    return i ^ (i >> 1) ^ ((i & 1) << 8) ^ ((i & 1) << 9);
}

// Fused layer-1 gate M = RY*RX = [[a, b], [-conj(b), conj(a)]] on register bit K.
// SoA: re[], im[] are packed over 2 states; all coefficients broadcast-packed.
template<int K>
__device__ __forceinline__ void l1p(u64* re, u64* im,
                                    u64 ar, u64 ai, u64 br, u64 bi,
                                    u64 nai, u64 nbr, u64 nbi) {
#pragma unroll
    for (int p = 0; p < 16; ++p) {
        const int m0 = ((p >> K) << (K + 1)) | (p & ((1 << K) - 1));
        const int m1 = m0 | (1 << K);
        u64 a0r = re[m0], a0i = im[m0], a1r = re[m1], a1i = im[m1];
        u64 n0r = f2fma(ar,  a0r, f2fma(nai, a0i, f2fma(br, a1r, f2mul(nbi, a1i))));
        u64 n0i = f2fma(ar,  a0i, f2fma(ai,  a0r, f2fma(br, a1i, f2mul(bi,  a1r))));
        u64 n1r = f2fma(nbr, a0r, f2fma(nbi, a0i, f2fma(ar, a1r, f2mul(ai,  a1i))));
        u64 n1i = f2fma(nbr, a0i, f2fma(bi,  a0r, f2fma(ar, a1i, f2mul(nai, a1r))));
        re[m0] = n0r; im[m0] = n0i; re[m1] = n1r; im[m1] = n1i;
    }
}

// RY gate (real rotation) on register bit K, packed.
template<int K>
__device__ __forceinline__ void ryp(u64* re, u64* im, u64 c, u64 s, u64 ns) {
#pragma unroll
    for (int p = 0; p < 16; ++p) {
        const int m0 = ((p >> K) << (K + 1)) | (p & ((1 << K) - 1));
        const int m1 = m0 | (1 << K);
        u64 n0r = f2fma(c, re[m0], f2mul(ns, re[m1]));
        u64 n0i = f2fma(c, im[m0], f2mul(ns, im[m1]));
        u64 n1r = f2fma(s, re[m0], f2mul(c,  re[m1]));
        u64 n1i = f2fma(s, im[m0], f2mul(c,  im[m1]));
        re[m0] = n0r; im[m0] = n0i; re[m1] = n1r; im[m1] = n1i;
    }
}

__global__ __launch_bounds__(128, 2)
void qsa2_kernel(const float* __restrict__ x,
                 const float* __restrict__ rx0,
                 const float* __restrict__ ry0,
                 const float* __restrict__ ry1,
                 float* __restrict__ out)
{
    __shared__ u64 buf[WARPS_PER_BLK][DIM];   // per-warp remap buffer (8 KB each)
    __shared__ float coef[NW][6];

    const int tid = threadIdx.x;
    if (tid < NW) {
        float s, c, s0, c0, s1, c1;
        sincosf(0.5f * rx0[tid], &s,  &c);
        sincosf(0.5f * ry0[tid], &s0, &c0);
        sincosf(0.5f * ry1[tid], &s1, &c1);
        coef[tid][0] =  c0 * c;   // alpha.re
        coef[tid][1] =  s0 * s;   // alpha.im
        coef[tid][2] = -s0 * c;   // beta.re
        coef[tid][3] = -c0 * s;   // beta.im
        coef[tid][4] =  c1;
        coef[tid][5] =  s1;
    }
    __syncthreads();

    const int w = tid >> 5;
    const int t = tid & 31;
    const int wg = blockIdx.x * WARPS_PER_BLK + w;  // warp id 0..2047
    const int n0 = wg * 2;                          // states n0 (lane x), n0+1 (lane y)
    u64* sb = buf[w];

    // ---- Load + L2-normalize both states. Layout LA: i = (r<<5)|t. ----
    u64 re[32], im[32];
    const float* x0 = x + (size_t)n0 * DIM;
    const float* x1 = x0 + DIM;
    u64 sumsq = 0ull;
#pragma unroll
    for (int r = 0; r < 32; ++r) {
        u64 v = pk(x0[(r << 5) + t], x1[(r << 5) + t]);
        re[r] = v;
        sumsq = f2fma(v, v, sumsq);
    }
#pragma unroll
    for (int off = 16; off; off >>= 1)
        sumsq = f2add(sumsq, __shfl_xor_sync(0xffffffffu, sumsq, off));
    {
        float sx, sy;
        upk(sumsq, sx, sy);
        u64 inv = pk(1.f / fmaxf(sqrtf(sx), 1e-12f),
                     1.f / fmaxf(sqrtf(sy), 1e-12f));
#pragma unroll
        for (int r = 0; r < 32; ++r) re[r] = f2mul(re[r], inv);
    }

    // ---- Phase A: fused layer-1 on wires 0..4 (LA reg bits; wire q -> K=4-q) ----
    // Wire 0 (K=4) specialized for the purely-real initial state.
    {
        u64 ar = pkb(coef[0][0]), ai = pkb(coef[0][1]);
        u64 br = pkb(coef[0][2]), bi = pkb(coef[0][3]);
        u64 nai = pkb(-coef[0][1]), nbr = pkb(-coef[0][2]);
#pragma unroll
        for (int p = 0; p < 16; ++p) {
            u64 a0 = re[p], a1 = re[p + 16];
            re[p]      = f2fma(ar,  a0, f2mul(br,  a1));
            im[p]      = f2fma(ai,  a0, f2mul(bi,  a1));
            re[p + 16] = f2fma(nbr, a0, f2mul(ar,  a1));
            im[p + 16] = f2fma(bi,  a0, f2mul(nai, a1));
        }
    }
#pragma unroll
    for (int q = 1; q < 5; ++q) {
        u64 ar = pkb(coef[q][0]), ai = pkb(coef[q][1]);
        u64 br = pkb(coef[q][2]), bi = pkb(coef[q][3]);
        u64 nai = pkb(-coef[q][1]), nbr = pkb(-coef[q][2]), nbi = pkb(-coef[q][3]);
        switch (q) {
            case 1: l1p<3>(re, im, ar, ai, br, bi, nai, nbr, nbi); break;
            case 2: l1p<2>(re, im, ar, ai, br, bi, nai, nbr, nbi); break;
            case 3: l1p<1>(re, im, ar, ai, br, bi, nai, nbr, nbi); break;
            case 4: l1p<0>(re, im, ar, ai, br, bi, nai, nbr, nbi); break;
        }
    }

    // ---- Remap LA -> LB (transpose), re then im through one 8KB buffer ----
    __syncwarp();
#pragma unroll
    for (int r = 0; r < 32; ++r) sb[swz((r << 5) | t)] = re[r];
    __syncwarp();
#pragma unroll
    for (int r = 0; r < 32; ++r) re[r] = sb[swz((t << 5) | r)];
    __syncwarp();
#pragma unroll
    for (int r = 0; r < 32; ++r) sb[swz((r << 5) | t)] = im[r];
    __syncwarp();
#pragma unroll
    for (int r = 0; r < 32; ++r) im[r] = sb[swz((t << 5) | r)];

    // ---- Phase B: fused layer-1 on wires 5..9 (LB; wire q -> K=9-q) ----
#pragma unroll
    for (int q = 5; q < 10; ++q) {
        u64 ar = pkb(coef[q][0]), ai = pkb(coef[q][1]);
        u64 br = pkb(coef[q][2]), bi = pkb(coef[q][3]);
        u64 nai = pkb(-coef[q][1]), nbr = pkb(-coef[q][2]), nbi = pkb(-coef[q][3]);
        switch (q) {
            case 5: l1p<4>(re, im, ar, ai, br, bi, nai, nbr, nbi); break;
            case 6: l1p<3>(re, im, ar, ai, br, bi, nai, nbr, nbi); break;
            case 7: l1p<2>(re, im, ar, ai, br, bi, nai, nbr, nbi); break;
            case 8: l1p<1>(re, im, ar, ai, br, bi, nai, nbr, nbi); break;
            case 9: l1p<0>(re, im, ar, ai, br, bi, nai, nbr, nbi); break;
        }
    }

    // ---- Remap LB -> LA with the CNOT-ring gather folded in ----
    __syncwarp();
#pragma unroll
    for (int r = 0; r < 32; ++r) sb[swz((t << 5) | r)] = re[r];
    __syncwarp();
#pragma unroll
    for (int r = 0; r < 32; ++r) re[r] = sb[swz(cnot_gather((r << 5) | t))];
    __syncwarp();
#pragma unroll
    for (int r = 0; r < 32; ++r) sb[swz((t << 5) | r)] = im[r];
    __syncwarp();
#pragma unroll
    for (int r = 0; r < 32; ++r) im[r] = sb[swz(cnot_gather((r << 5) | t))];

    // ---- Phase C: layer-2 RY on wires 0..4 ----
#pragma unroll
    for (int q = 0; q < 5; ++q) {
        u64 c = pkb(coef[q][4]), s = pkb(coef[q][5]), ns = pkb(-coef[q][5]);
        switch (q) {
            case 0: ryp<4>(re, im, c, s, ns); break;
            case 1: ryp<3>(re, im, c, s, ns); break;
            case 2: ryp<2>(re, im, c, s, ns); break;
            case 3: ryp<1>(re, im, c, s, ns); break;
            case 4: ryp<0>(re, im, c, s, ns); break;
        }
    }

    // ---- Remap LA -> LB (transpose) ----
    __syncwarp();
#pragma unroll
    for (int r = 0; r < 32; ++r) sb[swz((r << 5) | t)] = re[r];
    __syncwarp();
#pragma unroll
    for (int r = 0; r < 32; ++r) re[r] = sb[swz((t << 5) | r)];
    __syncwarp();
#pragma unroll
    for (int r = 0; r < 32; ++r) sb[swz((r << 5) | t)] = im[r];
    __syncwarp();
#pragma unroll
    for (int r = 0; r < 32; ++r) im[r] = sb[swz((t << 5) | r)];

    // ---- Phase D: layer-2 RY on wires 5..9 ----
#pragma unroll
    for (int q = 5; q < 10; ++q) {
        u64 c = pkb(coef[q][4]), s = pkb(coef[q][5]), ns = pkb(-coef[q][5]);
        switch (q) {
            case 5: ryp<4>(re, im, c, s, ns); break;
            case 6: ryp<3>(re, im, c, s, ns); break;
            case 7: ryp<2>(re, im, c, s, ns); break;
            case 8: ryp<1>(re, im, c, s, ns); break;
            case 9: ryp<0>(re, im, c, s, ns); break;
        }
    }

    // ---- Z expectations (packed). Layout LB: i = (t<<5)|r. ----
    const u64 NEG1 = pkb(-1.0f);
    u64 tot = 0, S0 = 0, S1 = 0, S2 = 0, S3 = 0, S4 = 0;
#pragma unroll
    for (int r = 0; r < 32; ++r) {
        u64 p = f2fma(re[r], re[r], f2mul(im[r], im[r]));
        tot = f2add(tot, p);
        S0 = (r & 1)  ? f2fma(p, NEG1, S0) : f2add(S0, p);
        S1 = (r & 2)  ? f2fma(p, NEG1, S1) : f2add(S1, p);
        S2 = (r & 4)  ? f2fma(p, NEG1, S2) : f2add(S2, p);
        S3 = (r & 8)  ? f2fma(p, NEG1, S3) : f2add(S3, p);
        S4 = (r & 16) ? f2fma(p, NEG1, S4) : f2add(S4, p);
    }
    u64 ntot = f2mul(tot, NEG1);
    u64 vals[10];
    vals[0] = (t & 16) ? ntot : tot;   // wire 0: t bit 4
    vals[1] = (t & 8)  ? ntot : tot;
    vals[2] = (t & 4)  ? ntot : tot;
    vals[3] = (t & 2)  ? ntot : tot;
    vals[4] = (t & 1)  ? ntot : tot;
    vals[5] = S4;                      // wire 5: r bit 4
    vals[6] = S3;
    vals[7] = S2;
    vals[8] = S1;
    vals[9] = S0;
#pragma unroll
    for (int off = 16; off; off >>= 1) {
#pragma unroll
        for (int j = 0; j < 10; ++j)
            vals[j] = f2add(vals[j], __shfl_xor_sync(0xffffffffu, vals[j], off));
    }
    if (t < 2) {
#pragma unroll
        for (int j = 0; j < 10; ++j) {
            float vx, vy;
            upk(vals[j], vx, vy);
            out[(size_t)(n0 + t) * NW + j] = t ? vy : vx;
        }
    }
}

extern "C" void kernel_launch(void* const* d_in, const int* in_sizes, int n_in,
                              void* d_out, int out_size) {
    const float* x   = (const float*)d_in[0];
    const float* rx0 = (const float*)d_in[1];
    const float* ry0 = (const float*)d_in[2];
    const float* ry1 = (const float*)d_in[3];
    float* out = (float*)d_out;
    const int n_states = in_sizes[0] / DIM;            // 4096
    const int n_warps  = n_states / 2;                 // 2048
    qsa2_kernel<<<n_warps / WARPS_PER_BLK, 32 * WARPS_PER_BLK>>>(x, rx0, ry0, ry1, out);
}

// round 3
// speedup vs baseline: 1.7409x; 1.7212x over previous
#include <cuda_runtime.h>

#define NW 10
#define DIM 1024
#define WARPS_PER_BLK 4

typedef unsigned long long u64;

// ---- packed f32x2 primitives ----
__device__ __forceinline__ u64 pk(float x, float y) {
    u64 r; asm("mov.b64 %0,{%1,%2};" : "=l"(r) : "f"(x), "f"(y)); return r;
}
__device__ __forceinline__ u64 pkb(float x) { return pk(x, x); }
__device__ __forceinline__ void upk(u64 a, float& x, float& y) {
    asm("mov.b64 {%0,%1},%2;" : "=f"(x), "=f"(y) : "l"(a));
}
__device__ __forceinline__ u64 f2fma(u64 a, u64 b, u64 c) {
    u64 d; asm("fma.rn.f32x2 %0,%1,%2,%3;" : "=l"(d) : "l"(a), "l"(b), "l"(c)); return d;
}
__device__ __forceinline__ u64 f2mul(u64 a, u64 b) {
    u64 d; asm("mul.rn.f32x2 %0,%1,%2;" : "=l"(d) : "l"(a), "l"(b)); return d;
}
// swap the two 32-bit halves: (re, im) -> (im, re)   [ALU pipe, not FMA]
__device__ __forceinline__ u64 swp(u64 a) {
    float x, y; upk(a, x, y); return pk(y, x);
}

// XOR swizzle for conflict-free 32x32 8-byte transpose through shared memory.
__device__ __forceinline__ int swz(int idx) {
    return (idx & 0x3E0) | (((idx >> 5) ^ idx) & 31);
}

// CNOT-ring gather: psi_after[i] = psi_before[g(i)]
__device__ __forceinline__ int cnot_gather(int i) {
    return i ^ (i >> 1) ^ ((i & 1) << 8) ^ ((i & 1) << 9);
}

// Fused layer-1 gate M = RY*RX = [[a, b], [-conj(b), conj(a)]] on register bit K.
// Amplitudes packed (re, im) in one u64. Coefficient vectors pre-packed:
//  arr=(ar,ar) naiai=(-ai,ai) ainai=(ai,-ai) brr=(br,br) nbrbr=(-br,-br) nbibi=(-bi,bi)
template<int K>
__device__ __forceinline__ void l1c(u64* a, u64 arr, u64 naiai, u64 ainai,
                                    u64 brr, u64 nbrbr, u64 nbibi) {
#pragma unroll
    for (int p = 0; p < 16; ++p) {
        const int m0 = ((p >> K) << (K + 1)) | (p & ((1 << K) - 1));
        const int m1 = m0 | (1 << K);
        u64 a0 = a[m0], a1 = a[m1];
        u64 s0 = swp(a0), s1 = swp(a1);
        u64 n0 = f2fma(arr,   a0, f2fma(naiai, s0, f2fma(brr, a1, f2mul(nbibi, s1))));
        u64 n1 = f2fma(nbrbr, a0, f2fma(nbibi, s0, f2fma(arr, a1, f2mul(ainai, s1))));
        a[m0] = n0; a[m1] = n1;
    }
}

// RY gate (real rotation) on register bit K: pure packed, no swaps.
template<int K>
__device__ __forceinline__ void ryc(u64* a, u64 cc, u64 ss, u64 nss) {
#pragma unroll
    for (int p = 0; p < 16; ++p) {
        const int m0 = ((p >> K) << (K + 1)) | (p & ((1 << K) - 1));
        const int m1 = m0 | (1 << K);
        u64 n0 = f2fma(cc, a[m0], f2mul(nss, a[m1]));
        u64 n1 = f2fma(ss, a[m0], f2mul(cc,  a[m1]));
        a[m0] = n0; a[m1] = n1;
    }
}

__global__ __launch_bounds__(128, 3)
void qsa3_kernel(const float* __restrict__ x,
                 const float* __restrict__ rx0,
                 const float* __restrict__ ry0,
                 const float* __restrict__ ry1,
                 float* __restrict__ out)
{
    __shared__ u64 buf[WARPS_PER_BLK][DIM];   // 8 KB per warp
    __shared__ float coef[NW][6];

    const int tid = threadIdx.x;
    if (tid < NW) {
        float s, c, s0, c0, s1, c1;
        sincosf(0.5f * rx0[tid], &s,  &c);
        sincosf(0.5f * ry0[tid], &s0, &c0);
        sincosf(0.5f * ry1[tid], &s1, &c1);
        coef[tid][0] =  c0 * c;   // alpha.re
        coef[tid][1] =  s0 * s;   // alpha.im
        coef[tid][2] = -s0 * c;   // beta.re
        coef[tid][3] = -c0 * s;   // beta.im
        coef[tid][4] =  c1;
        coef[tid][5] =  s1;
    }
    __syncthreads();

    const int w = tid >> 5;
    const int t = tid & 31;
    const int n = blockIdx.x * WARPS_PER_BLK + w;   // state 0..4095
    u64* sb = buf[w];

    // ---- Load + L2-normalize. Layout LA: i = (r<<5)|t. ----
    float v[32];
    const float* xr = x + (size_t)n * DIM;
    float sumsq = 0.f;
#pragma unroll
    for (int r = 0; r < 32; ++r) {
        v[r] = xr[(r << 5) + t];
        sumsq += v[r] * v[r];
    }
#pragma unroll
    for (int off = 16; off; off >>= 1)
        sumsq += __shfl_xor_sync(0xffffffffu, sumsq, off);
    const float inv = 1.f / fmaxf(sqrtf(sumsq), 1e-12f);
#pragma unroll
    for (int r = 0; r < 32; ++r) v[r] *= inv;

    // ---- Phase A: fused layer-1 on wires 0..4 (LA reg bits; wire q -> K=4-q) ----
    u64 a[32];
    {   // wire 0 (K=4), specialized for purely-real input
        u64 pa = pk(coef[0][0], coef[0][1]);    // (ar, ai)
        u64 pb = pk(coef[0][2], coef[0][3]);    // (br, bi)
        u64 pc = pk(-coef[0][2], coef[0][3]);   // (-br, bi)
        u64 pd = pk(coef[0][0], -coef[0][1]);   // (ar, -ai)
#pragma unroll
        for (int p = 0; p < 16; ++p) {
            u64 a0 = pkb(v[p]), a1 = pkb(v[p + 16]);
            a[p]      = f2fma(a0, pa, f2mul(a1, pb));
            a[p + 16] = f2fma(a0, pc, f2mul(a1, pd));
        }
    }
#pragma unroll
    for (int q = 1; q < 5; ++q) {
        float ar = coef[q][0], ai = coef[q][1], br = coef[q][2], bi = coef[q][3];
        u64 arr = pkb(ar), naiai = pk(-ai, ai), ainai = pk(ai, -ai);
        u64 brr = pkb(br), nbrbr = pkb(-br),    nbibi = pk(-bi, bi);
        switch (q) {
            case 1: l1c<3>(a, arr, naiai, ainai, brr, nbrbr, nbibi); break;
            case 2: l1c<2>(a, arr, naiai, ainai, brr, nbrbr, nbibi); break;
            case 3: l1c<1>(a, arr, naiai, ainai, brr, nbrbr, nbibi); break;
            case 4: l1c<0>(a, arr, naiai, ainai, brr, nbrbr, nbibi); break;
        }
    }

    // ---- Remap LA -> LB (transpose) ----
    __syncwarp();
#pragma unroll
    for (int r = 0; r < 32; ++r) sb[swz((r << 5) | t)] = a[r];
    __syncwarp();
#pragma unroll
    for (int r = 0; r < 32; ++r) a[r] = sb[swz((t << 5) | r)];

    // ---- Phase B: fused layer-1 on wires 5..9 (LB; wire q -> K=9-q) ----
#pragma unroll
    for (int q = 5; q < 10; ++q) {
        float ar = coef[q][0], ai = coef[q][1], br = coef[q][2], bi = coef[q][3];
        u64 arr = pkb(ar), naiai = pk(-ai, ai), ainai = pk(ai, -ai);
        u64 brr = pkb(br), nbrbr = pkb(-br),    nbibi = pk(-bi, bi);
        switch (q) {
            case 5: l1c<4>(a, arr, naiai, ainai, brr, nbrbr, nbibi); break;
            case 6: l1c<3>(a, arr, naiai, ainai, brr, nbrbr, nbibi); break;
            case 7: l1c<2>(a, arr, naiai, ainai, brr, nbrbr, nbibi); break;
            case 8: l1c<1>(a, arr, naiai, ainai, brr, nbrbr, nbibi); break;
            case 9: l1c<0>(a, arr, naiai, ainai, brr, nbrbr, nbibi); break;
        }
    }

    // ---- Remap LB -> LA with the CNOT-ring gather folded in ----
    __syncwarp();
#pragma unroll
    for (int r = 0; r < 32; ++r) sb[swz((t << 5) | r)] = a[r];
    __syncwarp();
#pragma unroll
    for (int r = 0; r < 32; ++r) a[r] = sb[swz(cnot_gather((r << 5) | t))];

    // ---- Phase C: layer-2 RY on wires 0..4 ----
#pragma unroll
    for (int q = 0; q < 5; ++q) {
        u64 cc = pkb(coef[q][4]), ss = pkb(coef[q][5]), nss = pkb(-coef[q][5]);
        switch (q) {
            case 0: ryc<4>(a, cc, ss, nss); break;
            case 1: ryc<3>(a, cc, ss, nss); break;
            case 2: ryc<2>(a, cc, ss, nss); break;
            case 3: ryc<1>(a, cc, ss, nss); break;
            case 4: ryc<0>(a, cc, ss, nss); break;
        }
    }

    // ---- Remap LA -> LB (transpose) ----
    __syncwarp();
#pragma unroll
    for (int r = 0; r < 32; ++r) sb[swz((r << 5) | t)] = a[r];
    __syncwarp();
#pragma unroll
    for (int r = 0; r < 32; ++r) a[r] = sb[swz((t << 5) | r)];

    // ---- Phase D: layer-2 RY on wires 5..9 ----
#pragma unroll
    for (int q = 5; q < 10; ++q) {
        u64 cc = pkb(coef[q][4]), ss = pkb(coef[q][5]), nss = pkb(-coef[q][5]);
        switch (q) {
            case 5: ryc<4>(a, cc, ss, nss); break;
            case 6: ryc<3>(a, cc, ss, nss); break;
            case 7: ryc<2>(a, cc, ss, nss); break;
            case 8: ryc<1>(a, cc, ss, nss); break;
            case 9: ryc<0>(a, cc, ss, nss); break;
        }
    }

    // ---- Z expectations. Layout LB: i = (t<<5)|r. Packed (re^2, im^2) accum. ----
    u64 tot = 0, S0 = 0, S1 = 0, S2 = 0, S3 = 0, S4 = 0;
    const u64 NEG1 = pkb(-1.0f);
#pragma unroll
    for (int r = 0; r < 32; ++r) {
        u64 p = f2mul(a[r], a[r]);                  // (re^2, im^2)
        tot = f2fma(p, pkb(1.0f), tot);
        S0 = (r & 1)  ? f2fma(p, NEG1, S0) : f2fma(p, pkb(1.0f), S0);
        S1 = (r & 2)  ? f2fma(p, NEG1, S1) : f2fma(p, pkb(1.0f), S1);
        S2 = (r & 4)  ? f2fma(p, NEG1, S2) : f2fma(p, pkb(1.0f), S2);
        S3 = (r & 8)  ? f2fma(p, NEG1, S3) : f2fma(p, pkb(1.0f), S3);
        S4 = (r & 16) ? f2fma(p, NEG1, S4) : f2fma(p, pkb(1.0f), S4);
    }
    // horizontal: prob = re^2 + im^2
    float vals[10];
    {
        float xx, yy;
        upk(tot, xx, yy); float ft = xx + yy;
        vals[0] = (t & 16) ? -ft : ft;   // wire 0: t bit 4
        vals[1] = (t & 8)  ? -ft : ft;
        vals[2] = (t & 4)  ? -ft : ft;
        vals[3] = (t & 2)  ? -ft : ft;
        vals[4] = (t & 1)  ? -ft : ft;
        upk(S4, xx, yy); vals[5] = xx + yy;   // wire 5: r bit 4
        upk(S3, xx, yy); vals[6] = xx + yy;
        upk(S2, xx, yy); vals[7] = xx + yy;
        upk(S1, xx, yy); vals[8] = xx + yy;
        upk(S0, xx, yy); vals[9] = xx + yy;
    }
#pragma unroll
    for (int off = 16; off; off >>= 1) {
#pragma unroll
        for (int j = 0; j < 10; ++j)
            vals[j] += __shfl_xor_sync(0xffffffffu, vals[j], off);
    }
    if (t == 0) {
#pragma unroll
        for (int j = 0; j < 10; ++j) out[(size_t)n * NW + j] = vals[j];
    }
}

extern "C" void kernel_launch(void* const* d_in, const int* in_sizes, int n_in,
                              void* d_out, int out_size) {
    const float* x   = (const float*)d_in[0];
    const float* rx0 = (const float*)d_in[1];
    const float* ry0 = (const float*)d_in[2];
    const float* ry1 = (const float*)d_in[3];
    float* out = (float*)d_out;
    const int n_states = in_sizes[0] / DIM;            // 4096
    qsa3_kernel<<<n_states / WARPS_PER_BLK, 32 * WARPS_PER_BLK>>>(x, rx0, ry0, ry1, out);
}